// round 4
// baseline (speedup 1.0000x reference)
#include <cuda_runtime.h>
#include <cuda_bf16.h>
#include <cstdint>

// Problem shapes
// enc [8,512,256], dec [8,640,128], W_enc [640,512], b_enc[640],
// W_pred [640,640], b_pred[640], W_out [1025,640], b_out[1025]
// out [8,256,128,1025] fp32
#define B_ 8
#define E_ 512
#define P_ 640
#define J_ 640
#define C_ 1025
#define T_ 256
#define U_ 128

// Scratch (static device memory, no allocation)
__device__ __align__(16) float g_e[2048 * 640];            // [B*T, J]
__device__ __align__(16) float g_p[1024 * 640];            // [B*U, J]
__device__ __align__(16) __nv_bfloat16 g_w[1025 * 640];    // W_out bf16

// ---------------------------------------------------------------------------
// Kernel 0: convert W_out to bf16
// ---------------------------------------------------------------------------
__global__ void convw_kernel(const float* __restrict__ w) {
    int i = blockIdx.x * 256 + threadIdx.x;
    if (i < (1025 * 640) / 4) {
        float4 v = *(const float4*)(w + (size_t)i * 4);
        *(__nv_bfloat162*)(g_w + (size_t)i * 4)     = __floats2bfloat162_rn(v.x, v.y);
        *(__nv_bfloat162*)(g_w + (size_t)i * 4 + 2) = __floats2bfloat162_rn(v.z, v.w);
    }
}

// ---------------------------------------------------------------------------
// Kernel 1: projection GEMM (fp32, exact)
//   out[row, j] = sum_k src[b, k, x] * W[j, k] + bias[j]
//   row = b*X + x, out row-major [M, 640]
//   which == 0 -> g_e, which == 1 -> g_p
// CTA tile 128x128, K-chunk 16, 256 threads, 8x8 microtile.
// ---------------------------------------------------------------------------
__global__ void __launch_bounds__(256) proj_kernel(
    const float* __restrict__ src, const float* __restrict__ W,
    const float* __restrict__ bias, int K, int X, int which)
{
    __shared__ float As[16][132];   // [k][m]
    __shared__ float Bs[16][132];   // [k][j]
    float* outp = which ? g_p : g_e;

    int m0 = blockIdx.x * 128;
    int j0 = blockIdx.y * 128;
    int b  = m0 / X;
    int x0 = m0 % X;
    int tid = threadIdx.x;
    int tm = tid & 15, tn = tid >> 4;

    float acc[8][8];
#pragma unroll
    for (int i = 0; i < 8; i++)
#pragma unroll
        for (int j = 0; j < 8; j++) acc[i][j] = 0.f;

    for (int k0 = 0; k0 < K; k0 += 16) {
        // A: src[b, k0+kk, x0 + ml], 16 x 128, coalesced along x
        {
            int kk = tid >> 5;            // 0..7
            int ml = (tid & 31) * 4;
            const float* s = src + ((size_t)b * K + k0 + kk) * X + x0 + ml;
            float4 v0 = *(const float4*)s;
            float4 v1 = *(const float4*)(s + (size_t)8 * X);
            *(float4*)&As[kk][ml]     = v0;
            *(float4*)&As[kk + 8][ml] = v1;
        }
        // W: [128 j][16 k] -> transpose into Bs[k][j]
        {
            int j  = tid >> 2;            // 0..63
            int k4 = (tid & 3) * 4;
#pragma unroll
            for (int pass = 0; pass < 2; pass++) {
                int jj = j + pass * 64;
                float4 v = *(const float4*)(W + (size_t)(j0 + jj) * K + k0 + k4);
                Bs[k4 + 0][jj] = v.x; Bs[k4 + 1][jj] = v.y;
                Bs[k4 + 2][jj] = v.z; Bs[k4 + 3][jj] = v.w;
            }
        }
        __syncthreads();
#pragma unroll
        for (int kk = 0; kk < 16; kk++) {
            float a[8], bb[8];
            *(float4*)(a)      = *(float4*)&As[kk][tm * 8];
            *(float4*)(a + 4)  = *(float4*)&As[kk][tm * 8 + 4];
            *(float4*)(bb)     = *(float4*)&Bs[kk][tn * 8];
            *(float4*)(bb + 4) = *(float4*)&Bs[kk][tn * 8 + 4];
#pragma unroll
            for (int i = 0; i < 8; i++)
#pragma unroll
                for (int j = 0; j < 8; j++) acc[i][j] += a[i] * bb[j];
        }
        __syncthreads();
    }
#pragma unroll
    for (int i = 0; i < 8; i++) {
        int m = m0 + tm * 8 + i;
        float* orow = outp + (size_t)m * 640 + j0 + tn * 8;
#pragma unroll
        for (int j = 0; j < 8; j++) orow[j] = acc[i][j] + bias[j0 + tn * 8 + j];
    }
}

// ---------------------------------------------------------------------------
// Kernel 2: fused joint + output GEMM + log_softmax
// One CTA per (b, t): h[128 u][640 j] = relu(e_bt + p_b) in bf16 smem.
// 8 n-tiles of 128 over c (0..1023) via mma.sync bf16; c=1024 via scalar dot.
// Online (max, sumexp) in smem; logits staged in d_out; final normalize pass.
// ---------------------------------------------------------------------------
#define HP 648                    // h smem pitch in bf16 (conflict-free ldmatrix)
#define WP 72                     // W tile smem pitch in bf16
#define HS_BYTES (128 * HP * 2)                  // 165888
#define WS_BYTES (2 * 128 * WP * 2)              // 36864
#define ST_BYTES ((512 + 512 + 128 + 128) * 4)   // 5120
#define SMEM_MAIN (HS_BYTES + WS_BYTES + ST_BYTES)

__device__ __forceinline__ uint32_t smem_u32(const void* p) {
    return (uint32_t)__cvta_generic_to_shared(p);
}
__device__ __forceinline__ void ldsm4(uint32_t* r, uint32_t addr) {
    asm volatile("ldmatrix.sync.aligned.m8n8.x4.shared.b16 {%0,%1,%2,%3}, [%4];"
                 : "=r"(r[0]), "=r"(r[1]), "=r"(r[2]), "=r"(r[3]) : "r"(addr));
}
__device__ __forceinline__ void mma16816(float* c, const uint32_t* a, const uint32_t* b) {
    asm volatile(
        "mma.sync.aligned.m16n8k16.row.col.f32.bf16.bf16.f32 "
        "{%0,%1,%2,%3}, {%4,%5,%6,%7}, {%8,%9}, {%0,%1,%2,%3};"
        : "+f"(c[0]), "+f"(c[1]), "+f"(c[2]), "+f"(c[3])
        : "r"(a[0]), "r"(a[1]), "r"(a[2]), "r"(a[3]), "r"(b[0]), "r"(b[1]));
}
__device__ __forceinline__ void cp_async16(uint32_t dst, const void* src) {
    asm volatile("cp.async.cg.shared.global [%0], [%1], 16;\n" :: "r"(dst), "l"(src));
}

__global__ void __launch_bounds__(256, 1) joint_kernel(
    const float* __restrict__ bout, float* __restrict__ out)
{
    extern __shared__ char smem[];
    __nv_bfloat16* hs = (__nv_bfloat16*)smem;
    __nv_bfloat16* ws = (__nv_bfloat16*)(smem + HS_BYTES);
    float* wmaxs = (float*)(smem + HS_BYTES + WS_BYTES);   // [4][128]
    float* wsums = wmaxs + 512;                            // [4][128]
    float* runM  = wsums + 512;                            // [128]
    float* runS  = runM + 128;                             // [128]

    const uint32_t hsm_base = smem_u32(hs);
    const uint32_t wsm_base = smem_u32(ws);

    int bt = blockIdx.x;                 // 0..2047
    int b  = bt >> 8;                    // T = 256
    const float* e_row = g_e + (size_t)bt * 640;
    const float* p_blk = g_p + (size_t)b * 128 * 640;
    float* out_blk = out + (size_t)bt * 128 * 1025;

    int tid  = threadIdx.x;
    int lane = tid & 31;
    int warp = tid >> 5;
    int wm = warp >> 2;                  // 0..1 (m)
    int wn = warp & 3;                   // 0..3 (n)

    // ---- build h = bf16(relu(e + p)) into smem ----
#pragma unroll 4
    for (int it = 0; it < 80; it++) {
        int idx = (it * 256 + tid) * 4;  // into 128*640
        int u = idx / 640, j = idx - u * 640;
        float4 pv = *(const float4*)(p_blk + (size_t)u * 640 + j);
        float4 ev = *(const float4*)(e_row + j);
        float h0 = fmaxf(ev.x + pv.x, 0.f);
        float h1 = fmaxf(ev.y + pv.y, 0.f);
        float h2 = fmaxf(ev.z + pv.z, 0.f);
        float h3 = fmaxf(ev.w + pv.w, 0.f);
        __nv_bfloat16* hp = hs + u * HP + j;
        *(__nv_bfloat162*)(hp)     = __floats2bfloat162_rn(h0, h1);
        *(__nv_bfloat162*)(hp + 2) = __floats2bfloat162_rn(h2, h3);
    }
    __syncthreads();

    // ---- special column c = 1024 (scalar dot, initializes running stats) ----
    {
        int u = tid >> 1, half = tid & 1;
        const uint4* hv4 = (const uint4*)(hs + u * HP + half * 320);
        const uint4* wv4 = (const uint4*)(g_w + (size_t)1024 * 640 + half * 320);
        float acc = 0.f;
#pragma unroll 4
        for (int it = 0; it < 40; it++) {
            uint4 hv = hv4[it];
            uint4 wv = wv4[it];
            const uint32_t* hu = (const uint32_t*)&hv;
            const uint32_t* wu = (const uint32_t*)&wv;
#pragma unroll
            for (int q = 0; q < 4; q++) {
                float2 hf = __bfloat1622float2(*(const __nv_bfloat162*)&hu[q]);
                float2 wf = __bfloat1622float2(*(const __nv_bfloat162*)&wu[q]);
                acc += hf.x * wf.x + hf.y * wf.y;
            }
        }
        acc += __shfl_xor_sync(0xffffffffu, acc, 1);
        if (half == 0) {
            float logit = acc + bout[1024];
            out_blk[(size_t)u * 1025 + 1024] = logit;
            runM[u] = logit;
            runS[u] = 1.0f;
        }
    }
    __syncthreads();

    // ---- 8 n-tiles of 128 columns ----
    for (int nt = 0; nt < 8; nt++) {
        const char* wg = (const char*)g_w + (size_t)nt * 128 * 1280;  // row pitch 1280B

        float acc[4][4][4];
#pragma unroll
        for (int i = 0; i < 4; i++)
#pragma unroll
            for (int j = 0; j < 4; j++)
#pragma unroll
                for (int q = 0; q < 4; q++) acc[i][j][q] = 0.f;

        // preload chunk 0 (buf 0)
        {
#pragma unroll
            for (int it = 0; it < 4; it++) {
                int idx = it * 256 + tid;
                int row = idx >> 3, v = idx & 7;
                cp_async16(wsm_base + row * 144 + v * 16,
                           wg + (size_t)row * 1280 + v * 16);
            }
        }
        asm volatile("cp.async.commit_group;\n" ::: "memory");

        for (int kc = 0; kc < 10; kc++) {
            if (kc < 9) {
                uint32_t sb = wsm_base + ((kc + 1) & 1) * (128 * WP * 2);
                const char* gb = wg + (size_t)(kc + 1) * 128;
#pragma unroll
                for (int it = 0; it < 4; it++) {
                    int idx = it * 256 + tid;
                    int row = idx >> 3, v = idx & 7;
                    cp_async16(sb + row * 144 + v * 16, gb + (size_t)row * 1280 + v * 16);
                }
            }
            asm volatile("cp.async.commit_group;\n" ::: "memory");
            asm volatile("cp.async.wait_group 1;\n" ::: "memory");
            __syncthreads();

            uint32_t wb_base = wsm_base + (kc & 1) * (128 * WP * 2);
#pragma unroll
            for (int ks = 0; ks < 4; ks++) {
                uint32_t a[4][4];
                int ar = wm * 64 + (lane & 15);
                int ak = kc * 64 + ks * 16 + (lane >> 4) * 8;
                uint32_t abase = hsm_base + (uint32_t)(ar * HP + ak) * 2;
#pragma unroll
                for (int mi = 0; mi < 4; mi++) ldsm4(a[mi], abase + mi * 16 * HP * 2);

                uint32_t bfr[2][4];
                int bn = (lane & 7) + ((lane >> 4) << 3);
                int bk = ks * 16 + ((lane >> 3) & 1) * 8;
                uint32_t bbase = wb_base + (uint32_t)((wn * 32 + bn) * WP + bk) * 2;
                ldsm4(bfr[0], bbase);
                ldsm4(bfr[1], bbase + 16 * WP * 2);

#pragma unroll
                for (int mi = 0; mi < 4; mi++)
#pragma unroll
                    for (int nj = 0; nj < 4; nj++)
                        mma16816(acc[mi][nj], a[mi], &bfr[nj >> 1][(nj & 1) * 2]);
            }
            __syncthreads();
        }

        // ---- epilogue: bias, write logits, per-row online stats ----
#pragma unroll
        for (int mi = 0; mi < 4; mi++) {
            int r0 = wm * 64 + mi * 16 + (lane >> 2);
#pragma unroll
            for (int nj = 0; nj < 4; nj++) {
                int col = wn * 32 + nj * 8 + (lane & 3) * 2;
                int c = nt * 128 + col;
                float b0 = bout[c], b1 = bout[c + 1];
                acc[mi][nj][0] += b0; acc[mi][nj][1] += b1;
                acc[mi][nj][2] += b0; acc[mi][nj][3] += b1;
                float* o0 = out_blk + (size_t)r0 * 1025 + c;
                o0[0] = acc[mi][nj][0]; o0[1] = acc[mi][nj][1];
                float* o1 = o0 + (size_t)8 * 1025;
                o1[0] = acc[mi][nj][2]; o1[1] = acc[mi][nj][3];
            }
#pragma unroll
            for (int rh = 0; rh < 2; rh++) {
                float m = -1e30f;
#pragma unroll
                for (int nj = 0; nj < 4; nj++) {
                    m = fmaxf(m, acc[mi][nj][rh * 2]);
                    m = fmaxf(m, acc[mi][nj][rh * 2 + 1]);
                }
                m = fmaxf(m, __shfl_xor_sync(0xffffffffu, m, 1));
                m = fmaxf(m, __shfl_xor_sync(0xffffffffu, m, 2));
                float s = 0.f;
#pragma unroll
                for (int nj = 0; nj < 4; nj++) {
                    s += __expf(acc[mi][nj][rh * 2] - m);
                    s += __expf(acc[mi][nj][rh * 2 + 1] - m);
                }
                s += __shfl_xor_sync(0xffffffffu, s, 1);
                s += __shfl_xor_sync(0xffffffffu, s, 2);
                if ((lane & 3) == 0) {
                    int r = r0 + rh * 8;
                    wmaxs[wn * 128 + r] = m;
                    wsums[wn * 128 + r] = s;
                }
            }
        }
        __syncthreads();
        if (tid < 128) {
            float m = wmaxs[tid], s = wsums[tid];
#pragma unroll
            for (int q = 1; q < 4; q++) {
                float m2 = wmaxs[q * 128 + tid], s2 = wsums[q * 128 + tid];
                float nm = fmaxf(m, m2);
                s = s * __expf(m - nm) + s2 * __expf(m2 - nm);
                m = nm;
            }
            float rm = runM[tid], rs = runS[tid];
            float nm = fmaxf(rm, m);
            runS[tid] = rs * __expf(rm - nm) + s * __expf(m - nm);
            runM[tid] = nm;
        }
        __syncthreads();
    }

    // ---- finalize: lse, then normalize logits in place ----
    if (tid < 128) runM[tid] = runM[tid] + logf(runS[tid]);
    __syncthreads();

    for (int i4 = tid; i4 < 32800; i4 += 256) {   // 128*1025/4
        float4* ptr = (float4*)out_blk + i4;
        float4 v = *ptr;
        int base = i4 * 4;
        v.x -= runM[base / 1025];
        v.y -= runM[(base + 1) / 1025];
        v.z -= runM[(base + 2) / 1025];
        v.w -= runM[(base + 3) / 1025];
        *ptr = v;
    }
}

// ---------------------------------------------------------------------------
extern "C" void kernel_launch(void* const* d_in, const int* in_sizes, int n_in,
                              void* d_out, int out_size) {
    const float* enc    = (const float*)d_in[0];
    const float* dec    = (const float*)d_in[1];
    const float* W_enc  = (const float*)d_in[2];
    const float* b_enc  = (const float*)d_in[3];
    const float* W_pred = (const float*)d_in[4];
    const float* b_pred = (const float*)d_in[5];
    const float* W_out  = (const float*)d_in[6];
    const float* b_out  = (const float*)d_in[7];
    float* out = (float*)d_out;

    convw_kernel<<<641, 256>>>(W_out);
    proj_kernel<<<dim3(16, 5), 256>>>(enc, W_enc, b_enc, E_, T_, 0);   // e
    proj_kernel<<<dim3(8, 5), 256>>>(dec, W_pred, b_pred, P_, U_, 1);  // p

    cudaFuncSetAttribute(joint_kernel,
                         cudaFuncAttributeMaxDynamicSharedMemorySize, SMEM_MAIN);
    joint_kernel<<<2048, 256, SMEM_MAIN>>>(b_out, out);
}